// round 12
// baseline (speedup 1.0000x reference)
#include <cuda_runtime.h>
#include <cstdint>

#define QMAXF 127.0f
#define EPSQ  1e-6f

static const int D = 4096;           // D_IN = D_OUT
static const int MROWS = 8192;       // B*S
static const int WELEMS = 4096 * 4096;

// ---- scratch (device globals; no allocation allowed) ----
__device__ double  g_partial[1024];
__device__ float   g_wscale;
__device__ float   g_rowf[8192];                 // per-row dequant factor = 1/s
__device__ int8_t  g_Wq[4096u * 4096u];          // ternary weights (int8)
__device__ int8_t  g_Xq[8192u * 4096u];          // quantized activations (int8)

__device__ __forceinline__ uint32_t smem_u32(const void* p) {
    uint32_t a;
    asm("{ .reg .u64 t; cvta.to.shared.u64 t, %1; cvt.u32.u64 %0, t; }" : "=r"(a) : "l"(p));
    return a;
}

// ============================================================================
// 1) fused prep: blocks [0,1024) -> sum|W| partials (4-acc unrolled, MLP>=4);
//    blocks [1024,9216) -> per-token activation quant. One launch.
// ============================================================================
static const int WSUM_BLOCKS = 1024;
static const int WSUM_ITERS = (WELEMS / 4) / (WSUM_BLOCKS * 256);   // 16

__global__ void k_prep(const float* __restrict__ W, const float* __restrict__ x) {
    if (blockIdx.x < WSUM_BLOCKS) {
        // ---- sum(|W|): 4 independent double accumulators, fully unrolled ----
        __shared__ double sh[256];
        const int stride = WSUM_BLOCKS * 256;
        const int base = blockIdx.x * 256 + threadIdx.x;
        const float4* W4 = reinterpret_cast<const float4*>(W);
        double a0 = 0.0, a1 = 0.0, a2 = 0.0, a3 = 0.0;
#pragma unroll
        for (int it = 0; it < WSUM_ITERS; it += 4) {
            float4 v0 = W4[base + (it + 0) * stride];
            float4 v1 = W4[base + (it + 1) * stride];
            float4 v2 = W4[base + (it + 2) * stride];
            float4 v3 = W4[base + (it + 3) * stride];
            a0 += (double)(fabsf(v0.x) + fabsf(v0.y)) + (double)(fabsf(v0.z) + fabsf(v0.w));
            a1 += (double)(fabsf(v1.x) + fabsf(v1.y)) + (double)(fabsf(v1.z) + fabsf(v1.w));
            a2 += (double)(fabsf(v2.x) + fabsf(v2.y)) + (double)(fabsf(v2.z) + fabsf(v2.w));
            a3 += (double)(fabsf(v3.x) + fabsf(v3.y)) + (double)(fabsf(v3.z) + fabsf(v3.w));
        }
        sh[threadIdx.x] = (a0 + a1) + (a2 + a3);
        __syncthreads();
        for (int s = 128; s > 0; s >>= 1) {
            if (threadIdx.x < s) sh[threadIdx.x] += sh[threadIdx.x + s];
            __syncthreads();
        }
        if (threadIdx.x == 0) g_partial[blockIdx.x] = sh[0];
    } else {
        // ---- per-token 8-bit activation quant -> int8 + row dequant factor ----
        __shared__ float sm[256];
        const int row = blockIdx.x - WSUM_BLOCKS;
        const float4* xr = reinterpret_cast<const float4*>(x + (size_t)row * D);
        float4 v[4];
        float mx = 0.0f;
#pragma unroll
        for (int j = 0; j < 4; j++) {
            v[j] = xr[threadIdx.x + 256 * j];
            mx = fmaxf(mx, fmaxf(fmaxf(fabsf(v[j].x), fabsf(v[j].y)),
                                 fmaxf(fabsf(v[j].z), fabsf(v[j].w))));
        }
        sm[threadIdx.x] = mx;
        __syncthreads();
        for (int s = 128; s > 0; s >>= 1) {
            if (threadIdx.x < s) sm[threadIdx.x] = fmaxf(sm[threadIdx.x], sm[threadIdx.x + s]);
            __syncthreads();
        }
        const float amax = fmaxf(sm[0], EPSQ);
        const float s = __fdiv_rn(QMAXF, amax);
        uint32_t* xq = reinterpret_cast<uint32_t*>(g_Xq) + (size_t)row * 1024;
#pragma unroll
        for (int j = 0; j < 4; j++) {
            int q0 = (int)fminf(fmaxf(rintf(v[j].x * s), -128.0f), 127.0f);
            int q1 = (int)fminf(fmaxf(rintf(v[j].y * s), -128.0f), 127.0f);
            int q2 = (int)fminf(fmaxf(rintf(v[j].z * s), -128.0f), 127.0f);
            int q3 = (int)fminf(fmaxf(rintf(v[j].w * s), -128.0f), 127.0f);
            xq[threadIdx.x + 256 * j] = (q0 & 0xFF) | ((q1 & 0xFF) << 8)
                                      | ((q2 & 0xFF) << 16) | ((uint32_t)(q3 & 0xFF) << 24);
        }
        if (threadIdx.x == 0) g_rowf[row] = __fdiv_rn(1.0f, s);
    }
}

// ============================================================================
// 2) finalize scale (redundantly per block, deterministic) + ternary quant W
// ============================================================================
__global__ void k_qw(const float* __restrict__ W) {
    __shared__ double sh[256];
    __shared__ float s_sc;
    {
        const int t = threadIdx.x;
        double a = g_partial[t] + g_partial[t + 256]
                 + g_partial[t + 512] + g_partial[t + 768];
        sh[t] = a;
        __syncthreads();
        for (int s = 128; s > 0; s >>= 1) {
            if (t < s) sh[t] += sh[t + s];
            __syncthreads();
        }
        if (t == 0) {
            float sc = (float)(sh[0] / (double)WELEMS);
            sc = fmaxf(sc, EPSQ);
            s_sc = sc;
            if (blockIdx.x == 0) g_wscale = sc;
        }
        __syncthreads();
    }
    const float sc = s_sc;
    const int n16 = WELEMS / 16;
    const int stride = gridDim.x * blockDim.x;
    for (int i = blockIdx.x * blockDim.x + threadIdx.x; i < n16; i += stride) {
        const float4* p = reinterpret_cast<const float4*>(W) + (size_t)i * 4;
        uint32_t packs[4];
#pragma unroll
        for (int j = 0; j < 4; j++) {
            float4 v = p[j];
            int q0 = (int)fminf(fmaxf(rintf(__fdiv_rn(v.x, sc)), -1.0f), 1.0f);
            int q1 = (int)fminf(fmaxf(rintf(__fdiv_rn(v.y, sc)), -1.0f), 1.0f);
            int q2 = (int)fminf(fmaxf(rintf(__fdiv_rn(v.z, sc)), -1.0f), 1.0f);
            int q3 = (int)fminf(fmaxf(rintf(__fdiv_rn(v.w, sc)), -1.0f), 1.0f);
            packs[j] = (q0 & 0xFF) | ((q1 & 0xFF) << 8) | ((q2 & 0xFF) << 16)
                     | ((uint32_t)(q3 & 0xFF) << 24);
        }
        uint4 u;
        u.x = packs[0]; u.y = packs[1]; u.z = packs[2]; u.w = packs[3];
        reinterpret_cast<uint4*>(g_Wq)[i] = u;
    }
}

// ============================================================================
// 3) int8 tensor-core GEMM: mma.sync.m16n8k32.s8  (exact integer math)
//    CTA tile 128x128x128, 8 warps (2m x 4n), warp tile 64x32.
//    3-stage cp.async (96KB smem) -> 2 CTAs/SM. (measured best: 94.9% tensor)
// ============================================================================
static const int BM = 128, BN = 128, BK = 128, STAGES = 3;
static const int KCHUNKS = 4096 / BK;            // 32
static const int TILEB  = BM * BK;               // 16384 bytes (int8)
static const int STAGEB = 2 * TILEB;             // 32768
static const int SMEM_TOTAL = STAGES * STAGEB;   // 98304

#define SW128(o) ((o) ^ (((o) >> 3) & 0x70))

__device__ __forceinline__ void cp_async16(uint32_t saddr, const void* gptr) {
    asm volatile("cp.async.cg.shared.global [%0], [%1], 16;" :: "r"(saddr), "l"(gptr));
}
__device__ __forceinline__ void ldmatrix_x4(uint32_t* r, uint32_t saddr) {
    asm volatile("ldmatrix.sync.aligned.m8n8.x4.shared.b16 {%0,%1,%2,%3}, [%4];"
                 : "=r"(r[0]), "=r"(r[1]), "=r"(r[2]), "=r"(r[3]) : "r"(saddr));
}
__device__ __forceinline__ void mma_s8(int* c, const uint32_t* a, uint32_t b0, uint32_t b1) {
    asm volatile("mma.sync.aligned.m16n8k32.row.col.s32.s8.s8.s32 "
                 "{%0,%1,%2,%3}, {%4,%5,%6,%7}, {%8,%9}, {%0,%1,%2,%3};"
                 : "+r"(c[0]), "+r"(c[1]), "+r"(c[2]), "+r"(c[3])
                 : "r"(a[0]), "r"(a[1]), "r"(a[2]), "r"(a[3]), "r"(b0), "r"(b1));
}

__global__ void __launch_bounds__(256, 2) k_gemm(const float* __restrict__ bias,
                                                 float* __restrict__ out) {
    extern __shared__ char smem[];
    const uint32_t sb = smem_u32(smem);
    const int tid = threadIdx.x;
    const int lane = tid & 31, wid = tid >> 5;
    const int warp_m = (wid >> 2) * 64;    // 2 warps along M
    const int warp_n = (wid & 3) * 32;     // 4 warps along N
    const int mbase = blockIdx.y * BM;
    const int nbase = blockIdx.x * BN;

    const int8_t* Ag = g_Xq + (size_t)mbase * D;
    const int8_t* Bg = g_Wq + (size_t)nbase * D;

    // cp.async geometry (hoisted): thread covers 8 rows spaced by 32
    const int ld_row = tid >> 3;
    const int ld_c16 = (tid & 7) * 16;
    const uint32_t sw_st = SW128((uint32_t)(ld_row * 128 + ld_c16));

    // ldmatrix base offsets (hoisted; swizzle applied per-kk)
    const uint32_t a_row_off[4] = {
        (uint32_t)((warp_m + 0 * 16 + (lane & 15)) * 128),
        (uint32_t)((warp_m + 1 * 16 + (lane & 15)) * 128),
        (uint32_t)((warp_m + 2 * 16 + (lane & 15)) * 128),
        (uint32_t)((warp_m + 3 * 16 + (lane & 15)) * 128)
    };
    const uint32_t b_row_off[2] = {
        (uint32_t)((warp_n + 0 * 16 + (lane & 15)) * 128),
        (uint32_t)((warp_n + 1 * 16 + (lane & 15)) * 128)
    };
    const uint32_t lane_colb = (uint32_t)((lane >> 4) * 16);

    int acc[4][4][4];
#pragma unroll
    for (int mt = 0; mt < 4; mt++)
#pragma unroll
        for (int nt = 0; nt < 4; nt++)
#pragma unroll
            for (int q = 0; q < 4; q++) acc[mt][nt][q] = 0;

    // ---- prologue: fill stages 0,1 ----
#pragma unroll
    for (int s = 0; s < STAGES - 1; s++) {
        const uint32_t base = sb + s * STAGEB;
#pragma unroll
        for (int j = 0; j < 4; j++) {
            const int row = ld_row + j * 32;
            const uint32_t dsw = sw_st + (uint32_t)(j * 32 * 128);
            cp_async16(base + dsw,         Ag + (size_t)row * D + s * BK + ld_c16);
            cp_async16(base + TILEB + dsw, Bg + (size_t)row * D + s * BK + ld_c16);
        }
        asm volatile("cp.async.commit_group;" ::: "memory");
    }

    // ---- mainloop (read stage rs, write stage ws = rs+2 mod 3) ----
    int rs = 0, ws = STAGES - 1;
    for (int kc = 0; kc < KCHUNKS; kc++) {
        asm volatile("cp.async.wait_group 1;" ::: "memory");
        __syncthreads();

        if (kc + STAGES - 1 < KCHUNKS) {
            const int kp = kc + STAGES - 1;
            const uint32_t base = sb + ws * STAGEB;
#pragma unroll
            for (int j = 0; j < 4; j++) {
                const int row = ld_row + j * 32;
                const uint32_t dsw = sw_st + (uint32_t)(j * 32 * 128);
                cp_async16(base + dsw,         Ag + (size_t)row * D + kp * BK + ld_c16);
                cp_async16(base + TILEB + dsw, Bg + (size_t)row * D + kp * BK + ld_c16);
            }
        }
        asm volatile("cp.async.commit_group;" ::: "memory");

        const uint32_t abase = sb + rs * STAGEB;
        const uint32_t bbase = abase + TILEB;

        // ---- kk loop with register double-buffering ----
        uint32_t a[2][4][4], b[2][2][4];
        {
            const uint32_t colb = lane_colb;     // kk = 0
#pragma unroll
            for (int mt = 0; mt < 4; mt++)
                ldmatrix_x4(a[0][mt], abase + SW128(a_row_off[mt] + colb));
#pragma unroll
            for (int bt = 0; bt < 2; bt++)
                ldmatrix_x4(b[0][bt], bbase + SW128(b_row_off[bt] + colb));
        }
#pragma unroll
        for (int kk = 0; kk < 4; kk++) {
            const int cur = kk & 1, nxt = cur ^ 1;
            if (kk < 3) {
                const uint32_t colb = (uint32_t)((kk + 1) * 32) + lane_colb;
#pragma unroll
                for (int mt = 0; mt < 4; mt++)
                    ldmatrix_x4(a[nxt][mt], abase + SW128(a_row_off[mt] + colb));
#pragma unroll
                for (int bt = 0; bt < 2; bt++)
                    ldmatrix_x4(b[nxt][bt], bbase + SW128(b_row_off[bt] + colb));
            }
#pragma unroll
            for (int mt = 0; mt < 4; mt++) {
#pragma unroll
                for (int nt = 0; nt < 4; nt++) {
                    const int bt = nt >> 1, h = nt & 1;
                    mma_s8(acc[mt][nt], a[cur][mt], b[cur][bt][h], b[cur][bt][h + 2]);
                }
            }
        }

        rs = (rs + 1 == STAGES) ? 0 : rs + 1;
        ws = (ws + 1 == STAGES) ? 0 : ws + 1;
    }

    // ---- epilogue: dequant + bias, f32 out ----
    const float wsc = g_wscale;
    float bv0[4], bv1[4];
#pragma unroll
    for (int nt = 0; nt < 4; nt++) {
        const int col = nbase + warp_n + nt * 8 + (lane & 3) * 2;
        bv0[nt] = bias[col];
        bv1[nt] = bias[col + 1];
    }
#pragma unroll
    for (int mt = 0; mt < 4; mt++) {
        const int r0 = mbase + warp_m + mt * 16 + (lane >> 2);
        const int r1 = r0 + 8;
        const float c0 = g_rowf[r0] * wsc;
        const float c1 = g_rowf[r1] * wsc;
        float* o0 = out + (size_t)r0 * D + nbase + warp_n;
        float* o1 = out + (size_t)r1 * D + nbase + warp_n;
#pragma unroll
        for (int nt = 0; nt < 4; nt++) {
            const int col = nt * 8 + (lane & 3) * 2;
            float2 v0, v1;
            v0.x = (float)acc[mt][nt][0] * c0 + bv0[nt];
            v0.y = (float)acc[mt][nt][1] * c0 + bv1[nt];
            v1.x = (float)acc[mt][nt][2] * c1 + bv0[nt];
            v1.y = (float)acc[mt][nt][3] * c1 + bv1[nt];
            *reinterpret_cast<float2*>(o0 + col) = v0;
            *reinterpret_cast<float2*>(o1 + col) = v1;
        }
    }
}

// ============================================================================
// launch
// ============================================================================
extern "C" void kernel_launch(void* const* d_in, const int* in_sizes, int n_in,
                              void* d_out, int out_size) {
    const float* x = (const float*)d_in[0];   // [4,2048,4096]
    const float* W = (const float*)d_in[1];   // [4096,4096]
    const float* b = (const float*)d_in[2];   // [4096]
    float* out = (float*)d_out;               // [4,2048,4096] f32

    k_prep<<<WSUM_BLOCKS + MROWS, 256>>>(W, x);   // wsum partials (MLP4) + qx
    k_qw<<<2048, 256>>>(W);                       // finalize scale + ternary W

    cudaFuncSetAttribute(k_gemm, cudaFuncAttributeMaxDynamicSharedMemorySize, SMEM_TOTAL);
    dim3 grid(D / BN, MROWS / BM);   // (32, 64) = 2048 CTAs, single launch
    k_gemm<<<grid, 256, SMEM_TOTAL>>>(b, out);

    (void)in_sizes; (void)n_in; (void)out_size;
}

// round 13
// speedup vs baseline: 1.0586x; 1.0586x over previous
#include <cuda_runtime.h>
#include <cstdint>

#define QMAXF 127.0f
#define EPSQ  1e-6f

static const int D = 4096;           // D_IN = D_OUT
static const int MROWS = 8192;       // B*S
static const int WELEMS = 4096 * 4096;

// ---- scratch (device globals; no allocation allowed) ----
__device__ double  g_partial[1024];
__device__ float   g_wscale;
__device__ float   g_rowf[8192];                 // per-row dequant factor = 1/s
__device__ int8_t  g_Wq[4096u * 4096u];          // ternary weights (int8)
__device__ int8_t  g_Xq[8192u * 4096u];          // quantized activations (int8)

__device__ __forceinline__ uint32_t smem_u32(const void* p) {
    uint32_t a;
    asm("{ .reg .u64 t; cvta.to.shared.u64 t, %1; cvt.u32.u64 %0, t; }" : "=r"(a) : "l"(p));
    return a;
}

// ============================================================================
// 1) fused prep: blocks [0,1024) -> sum|W| partials ; blocks [1024,9216) ->
//    per-token activation quant. Independent memory streams, one launch.
// ============================================================================
static const int WSUM_BLOCKS = 1024;

__global__ void k_prep(const float* __restrict__ W, const float* __restrict__ x) {
    if (blockIdx.x < WSUM_BLOCKS) {
        __shared__ double sh[256];
        double acc = 0.0;
        const int n4 = WELEMS / 4;
        const int stride = WSUM_BLOCKS * 256;
        for (int i = blockIdx.x * 256 + threadIdx.x; i < n4; i += stride) {
            float4 v = reinterpret_cast<const float4*>(W)[i];
            acc += (double)(fabsf(v.x) + fabsf(v.y)) + (double)(fabsf(v.z) + fabsf(v.w));
        }
        sh[threadIdx.x] = acc;
        __syncthreads();
        for (int s = 128; s > 0; s >>= 1) {
            if (threadIdx.x < s) sh[threadIdx.x] += sh[threadIdx.x + s];
            __syncthreads();
        }
        if (threadIdx.x == 0) g_partial[blockIdx.x] = sh[0];
    } else {
        __shared__ float sm[256];
        const int row = blockIdx.x - WSUM_BLOCKS;
        const float4* xr = reinterpret_cast<const float4*>(x + (size_t)row * D);
        float4 v[4];
        float mx = 0.0f;
#pragma unroll
        for (int j = 0; j < 4; j++) {
            v[j] = xr[threadIdx.x + 256 * j];
            mx = fmaxf(mx, fmaxf(fmaxf(fabsf(v[j].x), fabsf(v[j].y)),
                                 fmaxf(fabsf(v[j].z), fabsf(v[j].w))));
        }
        sm[threadIdx.x] = mx;
        __syncthreads();
        for (int s = 128; s > 0; s >>= 1) {
            if (threadIdx.x < s) sm[threadIdx.x] = fmaxf(sm[threadIdx.x], sm[threadIdx.x + s]);
            __syncthreads();
        }
        const float amax = fmaxf(sm[0], EPSQ);
        const float s = __fdiv_rn(QMAXF, amax);
        uint32_t* xq = reinterpret_cast<uint32_t*>(g_Xq) + (size_t)row * 1024;
#pragma unroll
        for (int j = 0; j < 4; j++) {
            int q0 = (int)fminf(fmaxf(rintf(v[j].x * s), -128.0f), 127.0f);
            int q1 = (int)fminf(fmaxf(rintf(v[j].y * s), -128.0f), 127.0f);
            int q2 = (int)fminf(fmaxf(rintf(v[j].z * s), -128.0f), 127.0f);
            int q3 = (int)fminf(fmaxf(rintf(v[j].w * s), -128.0f), 127.0f);
            xq[threadIdx.x + 256 * j] = (q0 & 0xFF) | ((q1 & 0xFF) << 8)
                                      | ((q2 & 0xFF) << 16) | ((uint32_t)(q3 & 0xFF) << 24);
        }
        if (threadIdx.x == 0) g_rowf[row] = __fdiv_rn(1.0f, s);
    }
}

// ============================================================================
// 2) finalize scale (redundantly per block, deterministic) + ternary quant W
// ============================================================================
__global__ void k_qw(const float* __restrict__ W) {
    __shared__ double sh[256];
    __shared__ float s_sc;
    {
        const int t = threadIdx.x;
        double a = g_partial[t] + g_partial[t + 256]
                 + g_partial[t + 512] + g_partial[t + 768];
        sh[t] = a;
        __syncthreads();
        for (int s = 128; s > 0; s >>= 1) {
            if (t < s) sh[t] += sh[t + s];
            __syncthreads();
        }
        if (t == 0) {
            float sc = (float)(sh[0] / (double)WELEMS);
            sc = fmaxf(sc, EPSQ);
            s_sc = sc;
            if (blockIdx.x == 0) g_wscale = sc;
        }
        __syncthreads();
    }
    const float sc = s_sc;
    const int n16 = WELEMS / 16;
    const int stride = gridDim.x * blockDim.x;
    for (int i = blockIdx.x * blockDim.x + threadIdx.x; i < n16; i += stride) {
        const float4* p = reinterpret_cast<const float4*>(W) + (size_t)i * 4;
        uint32_t packs[4];
#pragma unroll
        for (int j = 0; j < 4; j++) {
            float4 v = p[j];
            int q0 = (int)fminf(fmaxf(rintf(__fdiv_rn(v.x, sc)), -1.0f), 1.0f);
            int q1 = (int)fminf(fmaxf(rintf(__fdiv_rn(v.y, sc)), -1.0f), 1.0f);
            int q2 = (int)fminf(fmaxf(rintf(__fdiv_rn(v.z, sc)), -1.0f), 1.0f);
            int q3 = (int)fminf(fmaxf(rintf(__fdiv_rn(v.w, sc)), -1.0f), 1.0f);
            packs[j] = (q0 & 0xFF) | ((q1 & 0xFF) << 8) | ((q2 & 0xFF) << 16)
                     | ((uint32_t)(q3 & 0xFF) << 24);
        }
        uint4 u;
        u.x = packs[0]; u.y = packs[1]; u.z = packs[2]; u.w = packs[3];
        reinterpret_cast<uint4*>(g_Wq)[i] = u;
    }
}

// ============================================================================
// 3) int8 tensor-core GEMM: mma.sync.m16n8k32.s8  (exact integer math)
//    CTA tile 128x128x128, 8 warps (2m x 4n), warp tile 64x32.
//    3-stage cp.async (96KB smem) -> 2 CTAs/SM so sync bubbles overlap.
//    (measured best: 94.9% tensor; reproduced 1901.7/1901.6 us)
// ============================================================================
static const int BM = 128, BN = 128, BK = 128, STAGES = 3;
static const int KCHUNKS = 4096 / BK;            // 32
static const int TILEB  = BM * BK;               // 16384 bytes (int8)
static const int STAGEB = 2 * TILEB;             // 32768
static const int SMEM_TOTAL = STAGES * STAGEB;   // 98304

#define SW128(o) ((o) ^ (((o) >> 3) & 0x70))

__device__ __forceinline__ void cp_async16(uint32_t saddr, const void* gptr) {
    asm volatile("cp.async.cg.shared.global [%0], [%1], 16;" :: "r"(saddr), "l"(gptr));
}
__device__ __forceinline__ void ldmatrix_x4(uint32_t* r, uint32_t saddr) {
    asm volatile("ldmatrix.sync.aligned.m8n8.x4.shared.b16 {%0,%1,%2,%3}, [%4];"
                 : "=r"(r[0]), "=r"(r[1]), "=r"(r[2]), "=r"(r[3]) : "r"(saddr));
}
__device__ __forceinline__ void mma_s8(int* c, const uint32_t* a, uint32_t b0, uint32_t b1) {
    asm volatile("mma.sync.aligned.m16n8k32.row.col.s32.s8.s8.s32 "
                 "{%0,%1,%2,%3}, {%4,%5,%6,%7}, {%8,%9}, {%0,%1,%2,%3};"
                 : "+r"(c[0]), "+r"(c[1]), "+r"(c[2]), "+r"(c[3])
                 : "r"(a[0]), "r"(a[1]), "r"(a[2]), "r"(a[3]), "r"(b0), "r"(b1));
}

__global__ void __launch_bounds__(256, 2) k_gemm(const float* __restrict__ bias,
                                                 float* __restrict__ out) {
    extern __shared__ char smem[];
    const uint32_t sb = smem_u32(smem);
    const int tid = threadIdx.x;
    const int lane = tid & 31, wid = tid >> 5;
    const int warp_m = (wid >> 2) * 64;    // 2 warps along M
    const int warp_n = (wid & 3) * 32;     // 4 warps along N
    const int mbase = blockIdx.y * BM;
    const int nbase = blockIdx.x * BN;

    const int8_t* Ag = g_Xq + (size_t)mbase * D;
    const int8_t* Bg = g_Wq + (size_t)nbase * D;

    // cp.async geometry (hoisted): thread covers 8 rows spaced by 32
    const int ld_row = tid >> 3;
    const int ld_c16 = (tid & 7) * 16;
    const uint32_t sw_st = SW128((uint32_t)(ld_row * 128 + ld_c16));

    // ldmatrix base offsets (hoisted; swizzle applied per-kk)
    const uint32_t a_row_off[4] = {
        (uint32_t)((warp_m + 0 * 16 + (lane & 15)) * 128),
        (uint32_t)((warp_m + 1 * 16 + (lane & 15)) * 128),
        (uint32_t)((warp_m + 2 * 16 + (lane & 15)) * 128),
        (uint32_t)((warp_m + 3 * 16 + (lane & 15)) * 128)
    };
    const uint32_t b_row_off[2] = {
        (uint32_t)((warp_n + 0 * 16 + (lane & 15)) * 128),
        (uint32_t)((warp_n + 1 * 16 + (lane & 15)) * 128)
    };
    const uint32_t lane_colb = (uint32_t)((lane >> 4) * 16);

    int acc[4][4][4];
#pragma unroll
    for (int mt = 0; mt < 4; mt++)
#pragma unroll
        for (int nt = 0; nt < 4; nt++)
#pragma unroll
            for (int q = 0; q < 4; q++) acc[mt][nt][q] = 0;

    // ---- prologue: fill stages 0,1 ----
#pragma unroll
    for (int s = 0; s < STAGES - 1; s++) {
        const uint32_t base = sb + s * STAGEB;
#pragma unroll
        for (int j = 0; j < 4; j++) {
            const int row = ld_row + j * 32;
            const uint32_t dsw = sw_st + (uint32_t)(j * 32 * 128);
            cp_async16(base + dsw,         Ag + (size_t)row * D + s * BK + ld_c16);
            cp_async16(base + TILEB + dsw, Bg + (size_t)row * D + s * BK + ld_c16);
        }
        asm volatile("cp.async.commit_group;" ::: "memory");
    }

    // ---- mainloop (read stage rs, write stage ws = rs+2 mod 3) ----
    int rs = 0, ws = STAGES - 1;
    for (int kc = 0; kc < KCHUNKS; kc++) {
        asm volatile("cp.async.wait_group 1;" ::: "memory");
        __syncthreads();

        if (kc + STAGES - 1 < KCHUNKS) {
            const int kp = kc + STAGES - 1;
            const uint32_t base = sb + ws * STAGEB;
#pragma unroll
            for (int j = 0; j < 4; j++) {
                const int row = ld_row + j * 32;
                const uint32_t dsw = sw_st + (uint32_t)(j * 32 * 128);
                cp_async16(base + dsw,         Ag + (size_t)row * D + kp * BK + ld_c16);
                cp_async16(base + TILEB + dsw, Bg + (size_t)row * D + kp * BK + ld_c16);
            }
        }
        asm volatile("cp.async.commit_group;" ::: "memory");

        const uint32_t abase = sb + rs * STAGEB;
        const uint32_t bbase = abase + TILEB;

        // ---- kk loop with register double-buffering ----
        uint32_t a[2][4][4], b[2][2][4];
        {
            const uint32_t colb = lane_colb;     // kk = 0
#pragma unroll
            for (int mt = 0; mt < 4; mt++)
                ldmatrix_x4(a[0][mt], abase + SW128(a_row_off[mt] + colb));
#pragma unroll
            for (int bt = 0; bt < 2; bt++)
                ldmatrix_x4(b[0][bt], bbase + SW128(b_row_off[bt] + colb));
        }
#pragma unroll
        for (int kk = 0; kk < 4; kk++) {
            const int cur = kk & 1, nxt = cur ^ 1;
            if (kk < 3) {
                const uint32_t colb = (uint32_t)((kk + 1) * 32) + lane_colb;
#pragma unroll
                for (int mt = 0; mt < 4; mt++)
                    ldmatrix_x4(a[nxt][mt], abase + SW128(a_row_off[mt] + colb));
#pragma unroll
                for (int bt = 0; bt < 2; bt++)
                    ldmatrix_x4(b[nxt][bt], bbase + SW128(b_row_off[bt] + colb));
            }
#pragma unroll
            for (int mt = 0; mt < 4; mt++) {
#pragma unroll
                for (int nt = 0; nt < 4; nt++) {
                    const int bt = nt >> 1, h = nt & 1;
                    mma_s8(acc[mt][nt], a[cur][mt], b[cur][bt][h], b[cur][bt][h + 2]);
                }
            }
        }

        rs = (rs + 1 == STAGES) ? 0 : rs + 1;
        ws = (ws + 1 == STAGES) ? 0 : ws + 1;
    }

    // ---- epilogue: dequant + bias, f32 out ----
    const float wsc = g_wscale;
    float bv0[4], bv1[4];
#pragma unroll
    for (int nt = 0; nt < 4; nt++) {
        const int col = nbase + warp_n + nt * 8 + (lane & 3) * 2;
        bv0[nt] = bias[col];
        bv1[nt] = bias[col + 1];
    }
#pragma unroll
    for (int mt = 0; mt < 4; mt++) {
        const int r0 = mbase + warp_m + mt * 16 + (lane >> 2);
        const int r1 = r0 + 8;
        const float c0 = g_rowf[r0] * wsc;
        const float c1 = g_rowf[r1] * wsc;
        float* o0 = out + (size_t)r0 * D + nbase + warp_n;
        float* o1 = out + (size_t)r1 * D + nbase + warp_n;
#pragma unroll
        for (int nt = 0; nt < 4; nt++) {
            const int col = nt * 8 + (lane & 3) * 2;
            float2 v0, v1;
            v0.x = (float)acc[mt][nt][0] * c0 + bv0[nt];
            v0.y = (float)acc[mt][nt][1] * c0 + bv1[nt];
            v1.x = (float)acc[mt][nt][2] * c1 + bv0[nt];
            v1.y = (float)acc[mt][nt][3] * c1 + bv1[nt];
            *reinterpret_cast<float2*>(o0 + col) = v0;
            *reinterpret_cast<float2*>(o1 + col) = v1;
        }
    }
}

// ============================================================================
// launch
// ============================================================================
extern "C" void kernel_launch(void* const* d_in, const int* in_sizes, int n_in,
                              void* d_out, int out_size) {
    const float* x = (const float*)d_in[0];   // [4,2048,4096]
    const float* W = (const float*)d_in[1];   // [4096,4096]
    const float* b = (const float*)d_in[2];   // [4096]
    float* out = (float*)d_out;               // [4,2048,4096] f32

    k_prep<<<WSUM_BLOCKS + MROWS, 256>>>(W, x);   // wsum partials + activation quant
    k_qw<<<2048, 256>>>(W);                       // finalize scale + ternary W

    cudaFuncSetAttribute(k_gemm, cudaFuncAttributeMaxDynamicSharedMemorySize, SMEM_TOTAL);
    dim3 grid(D / BN, MROWS / BM);   // (32, 64) = 2048 CTAs, single launch
    k_gemm<<<grid, 256, SMEM_TOTAL>>>(b, out);

    (void)in_sizes; (void)n_in; (void)out_size;
}

// round 14
// speedup vs baseline: 1.0595x; 1.0009x over previous
#include <cuda_runtime.h>
#include <cstdint>

#define QMAXF 127.0f
#define EPSQ  1e-6f

static const int D = 4096;           // D_IN = D_OUT
static const int MROWS = 8192;       // B*S
static const int WELEMS = 4096 * 4096;

// ---- scratch (device globals; no allocation allowed) ----
__device__ double  g_partial[1024];
__device__ float   g_wscale;
__device__ float   g_rowf[8192];                 // per-row dequant factor = 1/s
__device__ int8_t  g_Wq[4096u * 4096u];          // ternary weights (int8)
__device__ int8_t  g_Xq[8192u * 4096u];          // quantized activations (int8)

__device__ __forceinline__ uint32_t smem_u32(const void* p) {
    uint32_t a;
    asm("{ .reg .u64 t; cvta.to.shared.u64 t, %1; cvt.u32.u64 %0, t; }" : "=r"(a) : "l"(p));
    return a;
}
__device__ __forceinline__ void cp_async16(uint32_t saddr, const void* gptr) {
    asm volatile("cp.async.cg.shared.global [%0], [%1], 16;" :: "r"(saddr), "l"(gptr));
}

// ============================================================================
// 1) fused prep: blocks [0,1024) -> sum|W| partials via cp.async ring (MLP=5,
//    zero extra registers); blocks [1024,9216) -> per-token activation quant
//    (textually identical to the measured-best version). One launch.
// ============================================================================
static const int WSUM_BLOCKS = 1024;
static const int WSUM_ITERS = (WELEMS / 4) / (WSUM_BLOCKS * 256);   // 16
static const int WRING = 6;                       // cp.async ring depth

__global__ void k_prep(const float* __restrict__ W, const float* __restrict__ x) {
    __shared__ __align__(16) char wbuf[WRING * 4096];   // 24KB ring (wsum branch)
    if (blockIdx.x < WSUM_BLOCKS) {
        __shared__ double sh[256];
        const int stride = WSUM_BLOCKS * 256;
        const int base = blockIdx.x * 256 + threadIdx.x;
        const float4* W4 = reinterpret_cast<const float4*>(W);
        const uint32_t slot0 = smem_u32(wbuf) + (uint32_t)threadIdx.x * 16;

        // prologue: 5 groups in flight
#pragma unroll
        for (int s = 0; s < WRING - 1; s++) {
            cp_async16(slot0 + (uint32_t)(s * 4096), &W4[base + s * stride]);
            asm volatile("cp.async.commit_group;" ::: "memory");
        }

        double acc = 0.0;
        for (int it = 0; it < WSUM_ITERS; it++) {
            asm volatile("cp.async.wait_group %0;" :: "n"(WRING - 2) : "memory");
            // each thread reads ONLY the float4 it wrote -> no barrier needed
            float4 v;
            asm volatile("ld.shared.v4.f32 {%0,%1,%2,%3}, [%4];"
                         : "=f"(v.x), "=f"(v.y), "=f"(v.z), "=f"(v.w)
                         : "r"(slot0 + (uint32_t)((it % WRING) * 4096)));
            acc += (double)(fabsf(v.x) + fabsf(v.y)) + (double)(fabsf(v.z) + fabsf(v.w));
            if (it + WRING - 1 < WSUM_ITERS) {
                cp_async16(slot0 + (uint32_t)(((it + WRING - 1) % WRING) * 4096),
                           &W4[base + (it + WRING - 1) * stride]);
            }
            asm volatile("cp.async.commit_group;" ::: "memory");
        }

        sh[threadIdx.x] = acc;
        __syncthreads();
        for (int s = 128; s > 0; s >>= 1) {
            if (threadIdx.x < s) sh[threadIdx.x] += sh[threadIdx.x + s];
            __syncthreads();
        }
        if (threadIdx.x == 0) g_partial[blockIdx.x] = sh[0];
    } else {
        __shared__ float sm[256];
        const int row = blockIdx.x - WSUM_BLOCKS;
        const float4* xr = reinterpret_cast<const float4*>(x + (size_t)row * D);
        float4 v[4];
        float mx = 0.0f;
#pragma unroll
        for (int j = 0; j < 4; j++) {
            v[j] = xr[threadIdx.x + 256 * j];
            mx = fmaxf(mx, fmaxf(fmaxf(fabsf(v[j].x), fabsf(v[j].y)),
                                 fmaxf(fabsf(v[j].z), fabsf(v[j].w))));
        }
        sm[threadIdx.x] = mx;
        __syncthreads();
        for (int s = 128; s > 0; s >>= 1) {
            if (threadIdx.x < s) sm[threadIdx.x] = fmaxf(sm[threadIdx.x], sm[threadIdx.x + s]);
            __syncthreads();
        }
        const float amax = fmaxf(sm[0], EPSQ);
        const float s = __fdiv_rn(QMAXF, amax);
        uint32_t* xq = reinterpret_cast<uint32_t*>(g_Xq) + (size_t)row * 1024;
#pragma unroll
        for (int j = 0; j < 4; j++) {
            int q0 = (int)fminf(fmaxf(rintf(v[j].x * s), -128.0f), 127.0f);
            int q1 = (int)fminf(fmaxf(rintf(v[j].y * s), -128.0f), 127.0f);
            int q2 = (int)fminf(fmaxf(rintf(v[j].z * s), -128.0f), 127.0f);
            int q3 = (int)fminf(fmaxf(rintf(v[j].w * s), -128.0f), 127.0f);
            xq[threadIdx.x + 256 * j] = (q0 & 0xFF) | ((q1 & 0xFF) << 8)
                                      | ((q2 & 0xFF) << 16) | ((uint32_t)(q3 & 0xFF) << 24);
        }
        if (threadIdx.x == 0) g_rowf[row] = __fdiv_rn(1.0f, s);
    }
}

// ============================================================================
// 2) finalize scale (redundantly per block, deterministic) + ternary quant W
// ============================================================================
__global__ void k_qw(const float* __restrict__ W) {
    __shared__ double sh[256];
    __shared__ float s_sc;
    {
        const int t = threadIdx.x;
        double a = g_partial[t] + g_partial[t + 256]
                 + g_partial[t + 512] + g_partial[t + 768];
        sh[t] = a;
        __syncthreads();
        for (int s = 128; s > 0; s >>= 1) {
            if (t < s) sh[t] += sh[t + s];
            __syncthreads();
        }
        if (t == 0) {
            float sc = (float)(sh[0] / (double)WELEMS);
            sc = fmaxf(sc, EPSQ);
            s_sc = sc;
            if (blockIdx.x == 0) g_wscale = sc;
        }
        __syncthreads();
    }
    const float sc = s_sc;
    const int n16 = WELEMS / 16;
    const int stride = gridDim.x * blockDim.x;
    for (int i = blockIdx.x * blockDim.x + threadIdx.x; i < n16; i += stride) {
        const float4* p = reinterpret_cast<const float4*>(W) + (size_t)i * 4;
        uint32_t packs[4];
#pragma unroll
        for (int j = 0; j < 4; j++) {
            float4 v = p[j];
            int q0 = (int)fminf(fmaxf(rintf(__fdiv_rn(v.x, sc)), -1.0f), 1.0f);
            int q1 = (int)fminf(fmaxf(rintf(__fdiv_rn(v.y, sc)), -1.0f), 1.0f);
            int q2 = (int)fminf(fmaxf(rintf(__fdiv_rn(v.z, sc)), -1.0f), 1.0f);
            int q3 = (int)fminf(fmaxf(rintf(__fdiv_rn(v.w, sc)), -1.0f), 1.0f);
            packs[j] = (q0 & 0xFF) | ((q1 & 0xFF) << 8) | ((q2 & 0xFF) << 16)
                     | ((uint32_t)(q3 & 0xFF) << 24);
        }
        uint4 u;
        u.x = packs[0]; u.y = packs[1]; u.z = packs[2]; u.w = packs[3];
        reinterpret_cast<uint4*>(g_Wq)[i] = u;
    }
}

// ============================================================================
// 3) int8 tensor-core GEMM: mma.sync.m16n8k32.s8  (exact integer math)
//    CTA tile 128x128x128, 8 warps (2m x 4n), warp tile 64x32.
//    3-stage cp.async (96KB smem) -> 2 CTAs/SM. (measured best: 94.9% tensor;
//    reproduced 1901.7/1901.6/1902.9 us — DO NOT TOUCH)
// ============================================================================
static const int BM = 128, BN = 128, BK = 128, STAGES = 3;
static const int KCHUNKS = 4096 / BK;            // 32
static const int TILEB  = BM * BK;               // 16384 bytes (int8)
static const int STAGEB = 2 * TILEB;             // 32768
static const int SMEM_TOTAL = STAGES * STAGEB;   // 98304

#define SW128(o) ((o) ^ (((o) >> 3) & 0x70))

__device__ __forceinline__ void ldmatrix_x4(uint32_t* r, uint32_t saddr) {
    asm volatile("ldmatrix.sync.aligned.m8n8.x4.shared.b16 {%0,%1,%2,%3}, [%4];"
                 : "=r"(r[0]), "=r"(r[1]), "=r"(r[2]), "=r"(r[3]) : "r"(saddr));
}
__device__ __forceinline__ void mma_s8(int* c, const uint32_t* a, uint32_t b0, uint32_t b1) {
    asm volatile("mma.sync.aligned.m16n8k32.row.col.s32.s8.s8.s32 "
                 "{%0,%1,%2,%3}, {%4,%5,%6,%7}, {%8,%9}, {%0,%1,%2,%3};"
                 : "+r"(c[0]), "+r"(c[1]), "+r"(c[2]), "+r"(c[3])
                 : "r"(a[0]), "r"(a[1]), "r"(a[2]), "r"(a[3]), "r"(b0), "r"(b1));
}

__global__ void __launch_bounds__(256, 2) k_gemm(const float* __restrict__ bias,
                                                 float* __restrict__ out) {
    extern __shared__ char smem[];
    const uint32_t sb = smem_u32(smem);
    const int tid = threadIdx.x;
    const int lane = tid & 31, wid = tid >> 5;
    const int warp_m = (wid >> 2) * 64;    // 2 warps along M
    const int warp_n = (wid & 3) * 32;     // 4 warps along N
    const int mbase = blockIdx.y * BM;
    const int nbase = blockIdx.x * BN;

    const int8_t* Ag = g_Xq + (size_t)mbase * D;
    const int8_t* Bg = g_Wq + (size_t)nbase * D;

    // cp.async geometry (hoisted): thread covers 8 rows spaced by 32
    const int ld_row = tid >> 3;
    const int ld_c16 = (tid & 7) * 16;
    const uint32_t sw_st = SW128((uint32_t)(ld_row * 128 + ld_c16));

    // ldmatrix base offsets (hoisted; swizzle applied per-kk)
    const uint32_t a_row_off[4] = {
        (uint32_t)((warp_m + 0 * 16 + (lane & 15)) * 128),
        (uint32_t)((warp_m + 1 * 16 + (lane & 15)) * 128),
        (uint32_t)((warp_m + 2 * 16 + (lane & 15)) * 128),
        (uint32_t)((warp_m + 3 * 16 + (lane & 15)) * 128)
    };
    const uint32_t b_row_off[2] = {
        (uint32_t)((warp_n + 0 * 16 + (lane & 15)) * 128),
        (uint32_t)((warp_n + 1 * 16 + (lane & 15)) * 128)
    };
    const uint32_t lane_colb = (uint32_t)((lane >> 4) * 16);

    int acc[4][4][4];
#pragma unroll
    for (int mt = 0; mt < 4; mt++)
#pragma unroll
        for (int nt = 0; nt < 4; nt++)
#pragma unroll
            for (int q = 0; q < 4; q++) acc[mt][nt][q] = 0;

    // ---- prologue: fill stages 0,1 ----
#pragma unroll
    for (int s = 0; s < STAGES - 1; s++) {
        const uint32_t base = sb + s * STAGEB;
#pragma unroll
        for (int j = 0; j < 4; j++) {
            const int row = ld_row + j * 32;
            const uint32_t dsw = sw_st + (uint32_t)(j * 32 * 128);
            cp_async16(base + dsw,         Ag + (size_t)row * D + s * BK + ld_c16);
            cp_async16(base + TILEB + dsw, Bg + (size_t)row * D + s * BK + ld_c16);
        }
        asm volatile("cp.async.commit_group;" ::: "memory");
    }

    // ---- mainloop (read stage rs, write stage ws = rs+2 mod 3) ----
    int rs = 0, ws = STAGES - 1;
    for (int kc = 0; kc < KCHUNKS; kc++) {
        asm volatile("cp.async.wait_group 1;" ::: "memory");
        __syncthreads();

        if (kc + STAGES - 1 < KCHUNKS) {
            const int kp = kc + STAGES - 1;
            const uint32_t base = sb + ws * STAGEB;
#pragma unroll
            for (int j = 0; j < 4; j++) {
                const int row = ld_row + j * 32;
                const uint32_t dsw = sw_st + (uint32_t)(j * 32 * 128);
                cp_async16(base + dsw,         Ag + (size_t)row * D + kp * BK + ld_c16);
                cp_async16(base + TILEB + dsw, Bg + (size_t)row * D + kp * BK + ld_c16);
            }
        }
        asm volatile("cp.async.commit_group;" ::: "memory");

        const uint32_t abase = sb + rs * STAGEB;
        const uint32_t bbase = abase + TILEB;

        // ---- kk loop with register double-buffering ----
        uint32_t a[2][4][4], b[2][2][4];
        {
            const uint32_t colb = lane_colb;     // kk = 0
#pragma unroll
            for (int mt = 0; mt < 4; mt++)
                ldmatrix_x4(a[0][mt], abase + SW128(a_row_off[mt] + colb));
#pragma unroll
            for (int bt = 0; bt < 2; bt++)
                ldmatrix_x4(b[0][bt], bbase + SW128(b_row_off[bt] + colb));
        }
#pragma unroll
        for (int kk = 0; kk < 4; kk++) {
            const int cur = kk & 1, nxt = cur ^ 1;
            if (kk < 3) {
                const uint32_t colb = (uint32_t)((kk + 1) * 32) + lane_colb;
#pragma unroll
                for (int mt = 0; mt < 4; mt++)
                    ldmatrix_x4(a[nxt][mt], abase + SW128(a_row_off[mt] + colb));
#pragma unroll
                for (int bt = 0; bt < 2; bt++)
                    ldmatrix_x4(b[nxt][bt], bbase + SW128(b_row_off[bt] + colb));
            }
#pragma unroll
            for (int mt = 0; mt < 4; mt++) {
#pragma unroll
                for (int nt = 0; nt < 4; nt++) {
                    const int bt = nt >> 1, h = nt & 1;
                    mma_s8(acc[mt][nt], a[cur][mt], b[cur][bt][h], b[cur][bt][h + 2]);
                }
            }
        }

        rs = (rs + 1 == STAGES) ? 0 : rs + 1;
        ws = (ws + 1 == STAGES) ? 0 : ws + 1;
    }

    // ---- epilogue: dequant + bias, f32 out ----
    const float wsc = g_wscale;
    float bv0[4], bv1[4];
#pragma unroll
    for (int nt = 0; nt < 4; nt++) {
        const int col = nbase + warp_n + nt * 8 + (lane & 3) * 2;
        bv0[nt] = bias[col];
        bv1[nt] = bias[col + 1];
    }
#pragma unroll
    for (int mt = 0; mt < 4; mt++) {
        const int r0 = mbase + warp_m + mt * 16 + (lane >> 2);
        const int r1 = r0 + 8;
        const float c0 = g_rowf[r0] * wsc;
        const float c1 = g_rowf[r1] * wsc;
        float* o0 = out + (size_t)r0 * D + nbase + warp_n;
        float* o1 = out + (size_t)r1 * D + nbase + warp_n;
#pragma unroll
        for (int nt = 0; nt < 4; nt++) {
            const int col = nt * 8 + (lane & 3) * 2;
            float2 v0, v1;
            v0.x = (float)acc[mt][nt][0] * c0 + bv0[nt];
            v0.y = (float)acc[mt][nt][1] * c0 + bv1[nt];
            v1.x = (float)acc[mt][nt][2] * c1 + bv0[nt];
            v1.y = (float)acc[mt][nt][3] * c1 + bv1[nt];
            *reinterpret_cast<float2*>(o0 + col) = v0;
            *reinterpret_cast<float2*>(o1 + col) = v1;
        }
    }
}

// ============================================================================
// launch
// ============================================================================
extern "C" void kernel_launch(void* const* d_in, const int* in_sizes, int n_in,
                              void* d_out, int out_size) {
    const float* x = (const float*)d_in[0];   // [4,2048,4096]
    const float* W = (const float*)d_in[1];   // [4096,4096]
    const float* b = (const float*)d_in[2];   // [4096]
    float* out = (float*)d_out;               // [4,2048,4096] f32

    k_prep<<<WSUM_BLOCKS + MROWS, 256>>>(W, x);   // wsum (cp.async ring) + qx
    k_qw<<<2048, 256>>>(W);                       // finalize scale + ternary W

    cudaFuncSetAttribute(k_gemm, cudaFuncAttributeMaxDynamicSharedMemorySize, SMEM_TOTAL);
    dim3 grid(D / BN, MROWS / BM);   // (32, 64) = 2048 CTAs, single launch
    k_gemm<<<grid, 256, SMEM_TOTAL>>>(b, out);

    (void)in_sizes; (void)n_in; (void)out_size;
}